// round 6
// baseline (speedup 1.0000x reference)
#include <cuda_runtime.h>

#define BB 16
#define CC 64
#define HH 192
#define WW 192
#define HT 64   // pooled spatial size

// scratch (static device global -- no runtime allocation allowed)
__device__ float g_xtem[BB*CC*HT*HT];

// -------------------------------------------------------------------------
// Kernel 1: fused maxpool3x3(s1,p1) + blurpool(4x4, s3, reflect(1,2)),
// separable: vmax (rolling, 7 loads/5 rows) -> hmax -> vblur -> hblur.
// Block = (48,5) = 240 threads, 8 output rows x 64 cols of one plane.
// -------------------------------------------------------------------------
__global__ void k_pool(const float* __restrict__ x) {
    __shared__ float vm[25][192];  // vertical 3-max
    __shared__ float hm[25][192];  // 3x3 max
    __shared__ float cb[8][192];   // vertically blurred rows
    int plane  = blockIdx.y;
    int oh0    = blockIdx.x * 8;
    int prbase = 3*oh0 - 1;        // pr of vm row 0
    const float* xp = x + (size_t)plane * (HH*WW);
    int q  = threadIdx.x;          // 0..47 (column quad)
    int ry = threadIdx.y;          // 0..4

    // stage 1: rolling vertical 3-max. This thread owns vm rows ry*5..ry*5+4,
    // which need input rows (prbase+ry*5-1 .. prbase+ry*5+5), clamped.
    {
        int base = prbase + ry*5;
        float4 r[7];
        #pragma unroll
        for (int k = 0; k < 7; k++) {
            int rr = min(max(base + k - 1, 0), 191);
            r[k] = __ldg((const float4*)(xp + (size_t)rr*WW) + q);
        }
        #pragma unroll
        for (int k = 0; k < 5; k++) {
            float4 m;
            m.x = fmaxf(fmaxf(r[k].x, r[k+1].x), r[k+2].x);
            m.y = fmaxf(fmaxf(r[k].y, r[k+1].y), r[k+2].y);
            m.z = fmaxf(fmaxf(r[k].z, r[k+1].z), r[k+2].z);
            m.w = fmaxf(fmaxf(r[k].w, r[k+1].w), r[k+2].w);
            *((float4*)&vm[ry*5 + k][0] + q) = m;
        }
    }
    __syncthreads();

    // stage 2: horizontal 3-max (clamped)
    #pragma unroll
    for (int k = 0; k < 5; k++) {
        int rr = ry*5 + k;
        float4 v = *((float4*)&vm[rr][0] + q);
        float left  = vm[rr][max(4*q - 1, 0)];
        float right = vm[rr][min(4*q + 4, 191)];
        float4 m;
        m.x = fmaxf(fmaxf(left, v.x), v.y);
        m.y = fmaxf(fmaxf(v.x,  v.y), v.z);
        m.z = fmaxf(fmaxf(v.y,  v.z), v.w);
        m.w = fmaxf(fmaxf(v.z,  v.w), right);
        *((float4*)&hm[rr][0] + q) = m;
    }
    __syncthreads();

    // stage 3: vertical blur (1,3,3,1): taps hm rows 3*ohl+u; reflect pr=-1 -> 1
    #pragma unroll
    for (int k = 0; k < 2; k++) {
        int ohl = ry + k*5;
        if (ohl < 8) {
            int rbase = 3*ohl;
            int r0i = (oh0 + ohl == 0) ? 2 : rbase;  // reflect
            float4 t0 = *((float4*)&hm[r0i    ][0] + q);
            float4 t1 = *((float4*)&hm[rbase+1][0] + q);
            float4 t2 = *((float4*)&hm[rbase+2][0] + q);
            float4 t3 = *((float4*)&hm[rbase+3][0] + q);
            float4 o;
            o.x = t0.x + 3.f*t1.x + 3.f*t2.x + t3.x;
            o.y = t0.y + 3.f*t1.y + 3.f*t2.y + t3.y;
            o.z = t0.z + 3.f*t1.z + 3.f*t2.z + t3.z;
            o.w = t0.w + 3.f*t1.w + 3.f*t2.w + t3.w;
            *((float4*)&cb[ohl][0] + q) = o;
        }
    }
    __syncthreads();

    // stage 4: horizontal blur at cols 3*ow-1+v; reflect pc=-1 -> 1
    int tid = ry*48 + q;
    for (int i = tid; i < 512; i += 240) {
        int ohl = i >> 6, ow = i & 63;
        int cbase = 3*ow - 1;
        float s = cb[ohl][(cbase < 0) ? 1 : cbase]
                + 3.f*cb[ohl][cbase+1]
                + 3.f*cb[ohl][cbase+2]
                +      cb[ohl][cbase+3];
        g_xtem[(size_t)plane*(HT*HT) + (oh0+ohl)*HT + ow] = s * (1.f/64.f);
    }
}

// -------------------------------------------------------------------------
// Kernel 2 (fused): combined 87-tap stencil + BN + sigmoid -> gate in smem,
// then streamed out = x * gate[i/3, j/3] for the whole plane (coalesced).
// smem union: gate overwrites the input tile (safe: acc is register-resident
// before the sync). One block per (b,c) plane, 256 threads.
// -------------------------------------------------------------------------
__global__ void k_att(const float* __restrict__ wh1, const float* __restrict__ wv1,
                      const float* __restrict__ wh2, const float* __restrict__ wv2,
                      const float* __restrict__ gamma, const float* __restrict__ beta,
                      const float* __restrict__ mean,  const float* __restrict__ var,
                      const float* __restrict__ x,     float* __restrict__ out) {
    __shared__ float buf[76*80];    // phase A: tile (halo 6, stride 80, col off 8)
                                    // phase B: gate (64*64 floats at offset 0)
    __shared__ float wc[169];       // combined 13x13 stencil
    float* tile = buf;
    float* gs   = buf;
    int plane = blockIdx.x;
    int ch    = plane % CC;
    int tid   = threadIdx.x;

    float4 z4 = make_float4(0.f,0.f,0.f,0.f);
    for (int i = tid; i < (76*80)/4; i += 256) ((float4*)tile)[i] = z4;
    if (tid < 169) wc[tid] = 0.f;
    __syncthreads();
    if (tid < 33) { int a = tid/3  - 5, b = tid%3  - 1; wc[(a+6)*13 + (b+6)]   += wh1[ch*33 + tid]; }
    __syncthreads();
    if (tid < 33) { int a = tid/11 - 1, b = tid%11 - 5; wc[(a+6)*13 + (b+6)]   += wv1[ch*33 + tid]; }
    __syncthreads();
    if (tid < 33) { int a = tid/3  - 5, b = tid%3  - 1; wc[(a+6)*13 + (b-a+6)] += wh2[ch*33 + tid]; }
    __syncthreads();
    if (tid < 33) { int s = tid/11 - 1, t = tid%11 - 5; wc[(s-t+6)*13 + (t+6)] += wv2[ch*33 + tid]; }

    const float4* src = (const float4*)(g_xtem + (size_t)plane*(HT*HT));
    for (int i = tid; i < 1024; i += 256) {
        int r = i / 16, c4 = i % 16;
        *((float4*)&tile[(r+6)*80 + c4*4 + 8]) = src[i];
    }
    __syncthreads();

    // ---- phase A: stencil -> registers ----
    int lane = tid & 31, w = tid >> 5;
    int c  = (w & 1)*32 + lane;
    int r0 = (w >> 1)*16;
    float acc[16];
    #pragma unroll
    for (int k = 0; k < 16; k++) acc[k] = 0.f;

    constexpr int LO[13] = {5,-1,-1,-1,-1,-5,-5,-5,-3,-4,-5,-6,-5};
    constexpr int HI[13] = {5, 6, 5, 4, 3, 5, 5, 5, 1, 1, 1, 1,-5};
    #pragma unroll
    for (int d = 0; d < 13; d++) {
        int cidx = c + d + 2;
        float xr[28];
        #pragma unroll
        for (int m = LO[d]+6; m <= HI[d]+21; m++)
            xr[m] = tile[(r0 + m)*80 + cidx];
        #pragma unroll
        for (int di = LO[d]; di <= HI[d]; di++) {
            float wv = wc[(di+6)*13 + d];
            #pragma unroll
            for (int k = 0; k < 16; k++)
                acc[k] += wv * xr[k + di + 6];
        }
    }

    float inv = gamma[ch] * rsqrtf(var[ch] + 1e-5f);
    float b2  = beta[ch] - mean[ch]*inv;
    __syncthreads();   // all tile reads done -> safe to overwrite with gate
    #pragma unroll
    for (int k = 0; k < 16; k++) {
        float a = acc[k]*inv + b2;
        gs[(r0 + k)*64 + c] = 1.f / (1.f + __expf(-a));
    }
    __syncthreads();

    // ---- phase B: out = x * gate (3x nearest upsample), batched MLP ----
    const float4* xp4 = (const float4*)(x   + (size_t)plane*(HH*WW));
    float4*       op4 = (float4*)     (out + (size_t)plane*(HH*WW));
    #pragma unroll
    for (int bt = 0; bt < 6; ++bt) {
        float4 v[6];
        #pragma unroll
        for (int u = 0; u < 6; u++)
            v[u] = xp4[(bt*6 + u)*256 + tid];
        #pragma unroll
        for (int u = 0; u < 6; u++) {
            int i    = (bt*6 + u)*256 + tid;
            int rowi = i / 48;
            int j    = i - rowi*48;
            int gr   = rowi / 3;
            int q3   = j / 3;
            int rem  = j - 3*q3;
            const float* grow = gs + gr*64;
            float lo = grow[4*q3 + rem];
            float hi = grow[4*q3 + rem + 1];
            float4 o;
            o.x = v[u].x * lo;
            o.y = v[u].y * ((rem == 2) ? hi : lo);
            o.z = v[u].z * ((rem >= 1) ? hi : lo);
            o.w = v[u].w * hi;
            op4[i] = o;
        }
    }
}

extern "C" void kernel_launch(void* const* d_in, const int* in_sizes, int n_in,
                              void* d_out, int out_size) {
    const float* x     = (const float*)d_in[0];
    const float* wh1   = (const float*)d_in[1];
    const float* wv1   = (const float*)d_in[2];
    const float* wh2   = (const float*)d_in[3];
    const float* wv2   = (const float*)d_in[4];
    const float* gamma = (const float*)d_in[5];
    const float* beta  = (const float*)d_in[6];
    const float* mean  = (const float*)d_in[7];
    const float* var   = (const float*)d_in[8];
    float* out = (float*)d_out;

    k_pool<<<dim3(8, BB*CC), dim3(48, 5)>>>(x);
    k_att<<<BB*CC, 256>>>(wh1, wv1, wh2, wv2, gamma, beta, mean, var, x, out);
}

// round 8
// speedup vs baseline: 1.2270x; 1.2270x over previous
#include <cuda_runtime.h>

#define BB 16
#define CC 64
#define HH 192
#define WW 192
#define HT 64   // pooled spatial size

// scratch (static device globals -- no runtime allocation allowed)
__device__ float g_xtem[BB*CC*HT*HT];
__device__ float g_gate[BB*CC*HT*HT];

// -------------------------------------------------------------------------
// Kernel 1: fused maxpool3x3(s1,p1) + blurpool(4x4, s3, reflect(1,2)),
// separable: vmax (rolling, 7 loads/5 rows) -> hmax -> vblur -> hblur.
// Block = (48,5) = 240 threads, 8 output rows x 64 cols of one plane.
// -------------------------------------------------------------------------
__global__ void k_pool(const float* __restrict__ x) {
    __shared__ float vm[25][192];  // vertical 3-max
    __shared__ float hm[25][192];  // 3x3 max
    __shared__ float cb[8][192];   // vertically blurred rows
    int plane  = blockIdx.y;
    int oh0    = blockIdx.x * 8;
    int prbase = 3*oh0 - 1;        // pr of vm row 0
    const float* xp = x + (size_t)plane * (HH*WW);
    int q  = threadIdx.x;          // 0..47 (column quad)
    int ry = threadIdx.y;          // 0..4

    // stage 1: rolling vertical 3-max
    {
        int base = prbase + ry*5;
        float4 r[7];
        #pragma unroll
        for (int k = 0; k < 7; k++) {
            int rr = min(max(base + k - 1, 0), 191);
            r[k] = __ldg((const float4*)(xp + (size_t)rr*WW) + q);
        }
        #pragma unroll
        for (int k = 0; k < 5; k++) {
            float4 m;
            m.x = fmaxf(fmaxf(r[k].x, r[k+1].x), r[k+2].x);
            m.y = fmaxf(fmaxf(r[k].y, r[k+1].y), r[k+2].y);
            m.z = fmaxf(fmaxf(r[k].z, r[k+1].z), r[k+2].z);
            m.w = fmaxf(fmaxf(r[k].w, r[k+1].w), r[k+2].w);
            *((float4*)&vm[ry*5 + k][0] + q) = m;
        }
    }
    __syncthreads();

    // stage 2: horizontal 3-max (clamped)
    #pragma unroll
    for (int k = 0; k < 5; k++) {
        int rr = ry*5 + k;
        float4 v = *((float4*)&vm[rr][0] + q);
        float left  = vm[rr][max(4*q - 1, 0)];
        float right = vm[rr][min(4*q + 4, 191)];
        float4 m;
        m.x = fmaxf(fmaxf(left, v.x), v.y);
        m.y = fmaxf(fmaxf(v.x,  v.y), v.z);
        m.z = fmaxf(fmaxf(v.y,  v.z), v.w);
        m.w = fmaxf(fmaxf(v.z,  v.w), right);
        *((float4*)&hm[rr][0] + q) = m;
    }
    __syncthreads();

    // stage 3: vertical blur (1,3,3,1); reflect pr=-1 -> 1
    #pragma unroll
    for (int k = 0; k < 2; k++) {
        int ohl = ry + k*5;
        if (ohl < 8) {
            int rbase = 3*ohl;
            int r0i = (oh0 + ohl == 0) ? 2 : rbase;  // reflect
            float4 t0 = *((float4*)&hm[r0i    ][0] + q);
            float4 t1 = *((float4*)&hm[rbase+1][0] + q);
            float4 t2 = *((float4*)&hm[rbase+2][0] + q);
            float4 t3 = *((float4*)&hm[rbase+3][0] + q);
            float4 o;
            o.x = t0.x + 3.f*t1.x + 3.f*t2.x + t3.x;
            o.y = t0.y + 3.f*t1.y + 3.f*t2.y + t3.y;
            o.z = t0.z + 3.f*t1.z + 3.f*t2.z + t3.z;
            o.w = t0.w + 3.f*t1.w + 3.f*t2.w + t3.w;
            *((float4*)&cb[ohl][0] + q) = o;
        }
    }
    __syncthreads();

    // stage 4: horizontal blur; reflect pc=-1 -> 1
    int tid = ry*48 + q;
    for (int i = tid; i < 512; i += 240) {
        int ohl = i >> 6, ow = i & 63;
        int cbase = 3*ow - 1;
        float s = cb[ohl][(cbase < 0) ? 1 : cbase]
                + 3.f*cb[ohl][cbase+1]
                + 3.f*cb[ohl][cbase+2]
                +      cb[ohl][cbase+3];
        g_xtem[(size_t)plane*(HT*HT) + (oh0+ohl)*HT + ow] = s * (1.f/64.f);
    }
}

// -------------------------------------------------------------------------
// Kernel 2: combined 87-tap stencil + BN + sigmoid -> g_gate (global).
// One block per (b,c) plane, 256 threads.
// -------------------------------------------------------------------------
__global__ void k_att(const float* __restrict__ wh1, const float* __restrict__ wv1,
                      const float* __restrict__ wh2, const float* __restrict__ wv2,
                      const float* __restrict__ gamma, const float* __restrict__ beta,
                      const float* __restrict__ mean,  const float* __restrict__ var) {
    __shared__ float tile[76*80];   // 64x64 plane, halo 6, row stride 80, col off 8
    __shared__ float wc[169];       // combined 13x13 stencil
    int plane = blockIdx.x;
    int ch    = plane % CC;
    int tid   = threadIdx.x;

    float4 z4 = make_float4(0.f,0.f,0.f,0.f);
    for (int i = tid; i < (76*80)/4; i += 256) ((float4*)tile)[i] = z4;
    if (tid < 169) wc[tid] = 0.f;
    __syncthreads();
    if (tid < 33) { int a = tid/3  - 5, b = tid%3  - 1; wc[(a+6)*13 + (b+6)]   += wh1[ch*33 + tid]; }
    __syncthreads();
    if (tid < 33) { int a = tid/11 - 1, b = tid%11 - 5; wc[(a+6)*13 + (b+6)]   += wv1[ch*33 + tid]; }
    __syncthreads();
    if (tid < 33) { int a = tid/3  - 5, b = tid%3  - 1; wc[(a+6)*13 + (b-a+6)] += wh2[ch*33 + tid]; }
    __syncthreads();
    if (tid < 33) { int s = tid/11 - 1, t = tid%11 - 5; wc[(s-t+6)*13 + (t+6)] += wv2[ch*33 + tid]; }

    const float4* src = (const float4*)(g_xtem + (size_t)plane*(HT*HT));
    for (int i = tid; i < 1024; i += 256) {
        int r = i / 16, c4 = i % 16;
        *((float4*)&tile[(r+6)*80 + c4*4 + 8]) = src[i];
    }
    __syncthreads();

    int lane = tid & 31, w = tid >> 5;
    int c  = (w & 1)*32 + lane;
    int r0 = (w >> 1)*16;
    float acc[16];
    #pragma unroll
    for (int k = 0; k < 16; k++) acc[k] = 0.f;

    constexpr int LO[13] = {5,-1,-1,-1,-1,-5,-5,-5,-3,-4,-5,-6,-5};
    constexpr int HI[13] = {5, 6, 5, 4, 3, 5, 5, 5, 1, 1, 1, 1,-5};
    #pragma unroll
    for (int d = 0; d < 13; d++) {
        int cidx = c + d + 2;
        float xr[28];
        #pragma unroll
        for (int m = LO[d]+6; m <= HI[d]+21; m++)
            xr[m] = tile[(r0 + m)*80 + cidx];
        #pragma unroll
        for (int di = LO[d]; di <= HI[d]; di++) {
            float wv = wc[(di+6)*13 + d];
            #pragma unroll
            for (int k = 0; k < 16; k++)
                acc[k] += wv * xr[k + di + 6];
        }
    }

    float inv = gamma[ch] * rsqrtf(var[ch] + 1e-5f);
    float b2  = beta[ch] - mean[ch]*inv;
    float* gp = g_gate + (size_t)plane*(HT*HT);
    #pragma unroll
    for (int k = 0; k < 16; k++) {
        float a = acc[k]*inv + b2;
        gp[(r0 + k)*HT + c] = 1.f / (1.f + __expf(-a));
    }
}

// -------------------------------------------------------------------------
// Kernel 3: out = x * gate[i/3, j/3], linear gid, 4 float4/thread batched
// (MLP=4), fully coalesced. grid 4608 x 512. Gate is L2-resident (16.8MB).
// -------------------------------------------------------------------------
__global__ void __launch_bounds__(512) k_mul(const float* __restrict__ x,
                                             float* __restrict__ out) {
    int base = blockIdx.x * 2048 + threadIdx.x;   // float4 index, stride 512 per batch
    float4 v[4];
    #pragma unroll
    for (int k = 0; k < 4; k++)
        v[k] = __ldg((const float4*)x + base + k*512);
    #pragma unroll
    for (int k = 0; k < 4; k++) {
        int i    = base + k*512;
        int rowi = i / 48;               // global row (plane*192 + ir)
        int j    = i - rowi*48;          // float4 col 0..47
        int p    = rowi / 192;
        int ir   = rowi - p*192;
        int gr   = ir / 3;               // gate row
        int q3   = j / 3;
        int rem  = j - q3*3;
        const float* grow = g_gate + (size_t)p*(HT*HT) + gr*HT + 4*q3 + rem;
        float lo = __ldg(grow);
        float hi = __ldg(grow + 1);
        float4 o;
        o.x = v[k].x * lo;
        o.y = v[k].y * ((rem == 2) ? hi : lo);
        o.z = v[k].z * ((rem >= 1) ? hi : lo);
        o.w = v[k].w * hi;
        ((float4*)out)[i] = o;
    }
}

extern "C" void kernel_launch(void* const* d_in, const int* in_sizes, int n_in,
                              void* d_out, int out_size) {
    const float* x     = (const float*)d_in[0];
    const float* wh1   = (const float*)d_in[1];
    const float* wv1   = (const float*)d_in[2];
    const float* wh2   = (const float*)d_in[3];
    const float* wv2   = (const float*)d_in[4];
    const float* gamma = (const float*)d_in[5];
    const float* beta  = (const float*)d_in[6];
    const float* mean  = (const float*)d_in[7];
    const float* var   = (const float*)d_in[8];
    float* out = (float*)d_out;

    k_pool<<<dim3(8, BB*CC), dim3(48, 5)>>>(x);
    k_att<<<BB*CC, 256>>>(wh1, wv1, wh2, wv2, gamma, beta, mean, var);
    k_mul<<<4608, 512>>>(x, out);
}

// round 9
// speedup vs baseline: 1.2818x; 1.0447x over previous
#include <cuda_runtime.h>

#define BB 16
#define CC 64
#define HH 192
#define WW 192
#define HT 64   // pooled spatial size

// scratch (static device globals -- no runtime allocation allowed)
__device__ float g_xtem[BB*CC*HT*HT];
__device__ float g_gate[BB*CC*HT*HT];

// -------------------------------------------------------------------------
// Kernel 1: fused maxpool3x3(s1,p1) + blurpool(4x4, s3, reflect(1,2)),
// separable: vmax (rolling 3-row window) -> hmax (in place, boundary
// pre-read) -> vblur -> hblur.  Block = (48,5) = 240 threads,
// 8 output rows x 64 cols of one plane.  smem 25.2KB -> 6+ blocks/SM.
// -------------------------------------------------------------------------
__global__ void __launch_bounds__(240, 6) k_pool(const float* __restrict__ x) {
    __shared__ float vm[25][192];  // vertical 3-max, then 3x3-max in place
    __shared__ float cb[8][192];   // vertically blurred rows
    int plane  = blockIdx.y;
    int oh0    = blockIdx.x * 8;
    int prbase = 3*oh0 - 1;        // pr of vm row 0
    const float* xp = x + (size_t)plane * (HH*WW);
    int q  = threadIdx.x;          // 0..47 (column quad)
    int ry = threadIdx.y;          // 0..4

    // stage 1: rolling vertical 3-max, vm rows ry*5..ry*5+4
    {
        int base = prbase + ry*5;
        int ra = min(max(base-1, 0), 191);
        int rb = min(max(base,   0), 191);
        float4 r0 = __ldg((const float4*)(xp + (size_t)ra*WW) + q);
        float4 r1 = __ldg((const float4*)(xp + (size_t)rb*WW) + q);
        #pragma unroll
        for (int k = 0; k < 5; k++) {
            int rc = min(max(base+k+1, 0), 191);
            float4 r2 = __ldg((const float4*)(xp + (size_t)rc*WW) + q);
            float4 m;
            m.x = fmaxf(fmaxf(r0.x, r1.x), r2.x);
            m.y = fmaxf(fmaxf(r0.y, r1.y), r2.y);
            m.z = fmaxf(fmaxf(r0.z, r1.z), r2.z);
            m.w = fmaxf(fmaxf(r0.w, r1.w), r2.w);
            *((float4*)&vm[ry*5 + k][0] + q) = m;
            r0 = r1; r1 = r2;
        }
    }
    __syncthreads();

    // stage 2a: pre-read boundary scalars (before in-place overwrite)
    float lefts[5], rights[5];
    #pragma unroll
    for (int k = 0; k < 5; k++) {
        int rr = ry*5 + k;
        lefts[k]  = vm[rr][max(4*q - 1, 0)];
        rights[k] = vm[rr][min(4*q + 4, 191)];
    }
    __syncthreads();

    // stage 2b: in-place horizontal 3-max (own quad only)
    #pragma unroll
    for (int k = 0; k < 5; k++) {
        int rr = ry*5 + k;
        float4 v = *((float4*)&vm[rr][0] + q);
        float4 m;
        m.x = fmaxf(fmaxf(lefts[k], v.x), v.y);
        m.y = fmaxf(fmaxf(v.x,  v.y), v.z);
        m.z = fmaxf(fmaxf(v.y,  v.z), v.w);
        m.w = fmaxf(fmaxf(v.z,  v.w), rights[k]);
        *((float4*)&vm[rr][0] + q) = m;
    }
    __syncthreads();

    // stage 3: vertical blur (1,3,3,1); reflect pr=-1 -> 1
    #pragma unroll
    for (int k = 0; k < 2; k++) {
        int ohl = ry + k*5;
        if (ohl < 8) {
            int rbase = 3*ohl;
            int r0i = (oh0 + ohl == 0) ? 2 : rbase;  // reflect
            float4 t0 = *((float4*)&vm[r0i    ][0] + q);
            float4 t1 = *((float4*)&vm[rbase+1][0] + q);
            float4 t2 = *((float4*)&vm[rbase+2][0] + q);
            float4 t3 = *((float4*)&vm[rbase+3][0] + q);
            float4 o;
            o.x = t0.x + 3.f*t1.x + 3.f*t2.x + t3.x;
            o.y = t0.y + 3.f*t1.y + 3.f*t2.y + t3.y;
            o.z = t0.z + 3.f*t1.z + 3.f*t2.z + t3.z;
            o.w = t0.w + 3.f*t1.w + 3.f*t2.w + t3.w;
            *((float4*)&cb[ohl][0] + q) = o;
        }
    }
    __syncthreads();

    // stage 4: horizontal blur; reflect pc=-1 -> 1
    int tid = ry*48 + q;
    for (int i = tid; i < 512; i += 240) {
        int ohl = i >> 6, ow = i & 63;
        int cbase = 3*ow - 1;
        float s = cb[ohl][(cbase < 0) ? 1 : cbase]
                + 3.f*cb[ohl][cbase+1]
                + 3.f*cb[ohl][cbase+2]
                +      cb[ohl][cbase+3];
        g_xtem[(size_t)plane*(HT*HT) + (oh0+ohl)*HT + ow] = s * (1.f/64.f);
    }
}

// -------------------------------------------------------------------------
// Kernel 2: combined 87-tap stencil + BN + sigmoid -> g_gate (global).
// One block per (b,c) plane, 256 threads.
// -------------------------------------------------------------------------
__global__ void k_att(const float* __restrict__ wh1, const float* __restrict__ wv1,
                      const float* __restrict__ wh2, const float* __restrict__ wv2,
                      const float* __restrict__ gamma, const float* __restrict__ beta,
                      const float* __restrict__ mean,  const float* __restrict__ var) {
    __shared__ float tile[76*80];   // 64x64 plane, halo 6, row stride 80, col off 8
    __shared__ float wc[169];       // combined 13x13 stencil
    int plane = blockIdx.x;
    int ch    = plane % CC;
    int tid   = threadIdx.x;

    float4 z4 = make_float4(0.f,0.f,0.f,0.f);
    for (int i = tid; i < (76*80)/4; i += 256) ((float4*)tile)[i] = z4;
    if (tid < 169) wc[tid] = 0.f;
    __syncthreads();
    if (tid < 33) { int a = tid/3  - 5, b = tid%3  - 1; wc[(a+6)*13 + (b+6)]   += wh1[ch*33 + tid]; }
    __syncthreads();
    if (tid < 33) { int a = tid/11 - 1, b = tid%11 - 5; wc[(a+6)*13 + (b+6)]   += wv1[ch*33 + tid]; }
    __syncthreads();
    if (tid < 33) { int a = tid/3  - 5, b = tid%3  - 1; wc[(a+6)*13 + (b-a+6)] += wh2[ch*33 + tid]; }
    __syncthreads();
    if (tid < 33) { int s = tid/11 - 1, t = tid%11 - 5; wc[(s-t+6)*13 + (t+6)] += wv2[ch*33 + tid]; }

    const float4* src = (const float4*)(g_xtem + (size_t)plane*(HT*HT));
    for (int i = tid; i < 1024; i += 256) {
        int r = i / 16, c4 = i % 16;
        *((float4*)&tile[(r+6)*80 + c4*4 + 8]) = src[i];
    }
    __syncthreads();

    int lane = tid & 31, w = tid >> 5;
    int c  = (w & 1)*32 + lane;
    int r0 = (w >> 1)*16;
    float acc[16];
    #pragma unroll
    for (int k = 0; k < 16; k++) acc[k] = 0.f;

    constexpr int LO[13] = {5,-1,-1,-1,-1,-5,-5,-5,-3,-4,-5,-6,-5};
    constexpr int HI[13] = {5, 6, 5, 4, 3, 5, 5, 5, 1, 1, 1, 1,-5};
    #pragma unroll
    for (int d = 0; d < 13; d++) {
        int cidx = c + d + 2;
        float xr[28];
        #pragma unroll
        for (int m = LO[d]+6; m <= HI[d]+21; m++)
            xr[m] = tile[(r0 + m)*80 + cidx];
        #pragma unroll
        for (int di = LO[d]; di <= HI[d]; di++) {
            float wv = wc[(di+6)*13 + d];
            #pragma unroll
            for (int k = 0; k < 16; k++)
                acc[k] += wv * xr[k + di + 6];
        }
    }

    float inv = gamma[ch] * rsqrtf(var[ch] + 1e-5f);
    float b2  = beta[ch] - mean[ch]*inv;
    float* gp = g_gate + (size_t)plane*(HT*HT);
    #pragma unroll
    for (int k = 0; k < 16; k++) {
        float a = acc[k]*inv + b2;
        gp[(r0 + k)*HT + c] = 1.f / (1.f + __expf(-a));
    }
}

// -------------------------------------------------------------------------
// Kernel 3: out = x * gate[i/3, j/3].  Block = 24 rows of one plane
// (8 gate rows staged in smem).  384 threads, 3 float4/thread (batched),
// fully coalesced loads+stores.  grid (8, 1024).
// -------------------------------------------------------------------------
__global__ void __launch_bounds__(384) k_mul(const float* __restrict__ x,
                                             float* __restrict__ out) {
    __shared__ float gsm[8*64];        // 8 gate rows
    int plane = blockIdx.y;
    int grp   = blockIdx.x;            // 24-row group
    int tid   = threadIdx.x;

    const float4* gsrc = (const float4*)(g_gate + (size_t)plane*(HT*HT) + grp*8*HT);
    if (tid < 128) ((float4*)gsm)[tid] = gsrc[tid];
    __syncthreads();

    const float4* xp = (const float4*)x   + (size_t)plane*9216 + grp*1152;
    float4*       op = (float4*)out       + (size_t)plane*9216 + grp*1152;

    float4 v[3];
    #pragma unroll
    for (int k = 0; k < 3; k++)
        v[k] = __ldg(xp + tid + k*384);

    #pragma unroll
    for (int k = 0; k < 3; k++) {
        int i    = tid + k*384;        // 0..1151 within tile
        int rowl = i / 48;             // local row 0..23
        int j    = i - rowl*48;        // float4 col 0..47
        int grl  = rowl / 3;           // local gate row 0..7
        int q3   = j / 3;
        int rem  = j - q3*3;
        const float* grow = gsm + grl*64 + 4*q3 + rem;
        float lo = grow[0];
        float hi = grow[1];
        float4 o;
        o.x = v[k].x * lo;
        o.y = v[k].y * ((rem == 2) ? hi : lo);
        o.z = v[k].z * ((rem >= 1) ? hi : lo);
        o.w = v[k].w * hi;
        op[i] = o;
    }
}

extern "C" void kernel_launch(void* const* d_in, const int* in_sizes, int n_in,
                              void* d_out, int out_size) {
    const float* x     = (const float*)d_in[0];
    const float* wh1   = (const float*)d_in[1];
    const float* wv1   = (const float*)d_in[2];
    const float* wh2   = (const float*)d_in[3];
    const float* wv2   = (const float*)d_in[4];
    const float* gamma = (const float*)d_in[5];
    const float* beta  = (const float*)d_in[6];
    const float* mean  = (const float*)d_in[7];
    const float* var   = (const float*)d_in[8];
    float* out = (float*)d_out;

    k_pool<<<dim3(8, BB*CC), dim3(48, 5)>>>(x);
    k_att<<<BB*CC, 256>>>(wh1, wv1, wh2, wv2, gamma, beta, mean, var);
    k_mul<<<dim3(8, BB*CC), 384>>>(x, out);
}

// round 10
// speedup vs baseline: 1.2960x; 1.0111x over previous
#include <cuda_runtime.h>

#define BB 16
#define CC 64
#define HH 192
#define WW 192
#define HT 64   // pooled spatial size

// scratch (static device globals -- no runtime allocation allowed)
__device__ float g_xtem[BB*CC*HT*HT];
__device__ float g_gate[BB*CC*HT*HT];

// -------------------------------------------------------------------------
// Kernel 1: fused maxpool3x3(s1,p1) + blurpool(4x4, s3, reflect(1,2)),
// separable: vmax (rolling 3-row window) -> hmax (in place, boundary
// pre-read) -> vblur -> hblur.  Block = (48,5) = 240 threads,
// 8 output rows x 64 cols of one plane.  smem 25.2KB.
// -------------------------------------------------------------------------
__global__ void __launch_bounds__(240, 6) k_pool(const float* __restrict__ x) {
    __shared__ float vm[25][192];  // vertical 3-max, then 3x3-max in place
    __shared__ float cb[8][192];   // vertically blurred rows
    int plane  = blockIdx.y;
    int oh0    = blockIdx.x * 8;
    int prbase = 3*oh0 - 1;        // pr of vm row 0
    const float* xp = x + (size_t)plane * (HH*WW);
    int q  = threadIdx.x;          // 0..47 (column quad)
    int ry = threadIdx.y;          // 0..4

    // stage 1: rolling vertical 3-max, vm rows ry*5..ry*5+4
    {
        int base = prbase + ry*5;
        int ra = min(max(base-1, 0), 191);
        int rb = min(max(base,   0), 191);
        float4 r0 = __ldg((const float4*)(xp + (size_t)ra*WW) + q);
        float4 r1 = __ldg((const float4*)(xp + (size_t)rb*WW) + q);
        #pragma unroll
        for (int k = 0; k < 5; k++) {
            int rc = min(max(base+k+1, 0), 191);
            float4 r2 = __ldg((const float4*)(xp + (size_t)rc*WW) + q);
            float4 m;
            m.x = fmaxf(fmaxf(r0.x, r1.x), r2.x);
            m.y = fmaxf(fmaxf(r0.y, r1.y), r2.y);
            m.z = fmaxf(fmaxf(r0.z, r1.z), r2.z);
            m.w = fmaxf(fmaxf(r0.w, r1.w), r2.w);
            *((float4*)&vm[ry*5 + k][0] + q) = m;
            r0 = r1; r1 = r2;
        }
    }
    __syncthreads();

    // stage 2a: pre-read boundary scalars (before in-place overwrite)
    float lefts[5], rights[5];
    #pragma unroll
    for (int k = 0; k < 5; k++) {
        int rr = ry*5 + k;
        lefts[k]  = vm[rr][max(4*q - 1, 0)];
        rights[k] = vm[rr][min(4*q + 4, 191)];
    }
    __syncthreads();

    // stage 2b: in-place horizontal 3-max (own quad only)
    #pragma unroll
    for (int k = 0; k < 5; k++) {
        int rr = ry*5 + k;
        float4 v = *((float4*)&vm[rr][0] + q);
        float4 m;
        m.x = fmaxf(fmaxf(lefts[k], v.x), v.y);
        m.y = fmaxf(fmaxf(v.x,  v.y), v.z);
        m.z = fmaxf(fmaxf(v.y,  v.z), v.w);
        m.w = fmaxf(fmaxf(v.z,  v.w), rights[k]);
        *((float4*)&vm[rr][0] + q) = m;
    }
    __syncthreads();

    // stage 3: vertical blur (1,3,3,1); reflect pr=-1 -> 1
    #pragma unroll
    for (int k = 0; k < 2; k++) {
        int ohl = ry + k*5;
        if (ohl < 8) {
            int rbase = 3*ohl;
            int r0i = (oh0 + ohl == 0) ? 2 : rbase;  // reflect
            float4 t0 = *((float4*)&vm[r0i    ][0] + q);
            float4 t1 = *((float4*)&vm[rbase+1][0] + q);
            float4 t2 = *((float4*)&vm[rbase+2][0] + q);
            float4 t3 = *((float4*)&vm[rbase+3][0] + q);
            float4 o;
            o.x = t0.x + 3.f*t1.x + 3.f*t2.x + t3.x;
            o.y = t0.y + 3.f*t1.y + 3.f*t2.y + t3.y;
            o.z = t0.z + 3.f*t1.z + 3.f*t2.z + t3.z;
            o.w = t0.w + 3.f*t1.w + 3.f*t2.w + t3.w;
            *((float4*)&cb[ohl][0] + q) = o;
        }
    }
    __syncthreads();

    // stage 4: horizontal blur; reflect pc=-1 -> 1
    int tid = ry*48 + q;
    for (int i = tid; i < 512; i += 240) {
        int ohl = i >> 6, ow = i & 63;
        int cbase = 3*ow - 1;
        float s = cb[ohl][(cbase < 0) ? 1 : cbase]
                + 3.f*cb[ohl][cbase+1]
                + 3.f*cb[ohl][cbase+2]
                +      cb[ohl][cbase+3];
        g_xtem[(size_t)plane*(HT*HT) + (oh0+ohl)*HT + ow] = s * (1.f/64.f);
    }
}

// -------------------------------------------------------------------------
// Kernel 2: combined 87-tap stencil + BN + sigmoid -> g_gate (global).
// One block per (b,c) plane, 256 threads.
// -------------------------------------------------------------------------
__global__ void k_att(const float* __restrict__ wh1, const float* __restrict__ wv1,
                      const float* __restrict__ wh2, const float* __restrict__ wv2,
                      const float* __restrict__ gamma, const float* __restrict__ beta,
                      const float* __restrict__ mean,  const float* __restrict__ var) {
    __shared__ float tile[76*80];   // 64x64 plane, halo 6, row stride 80, col off 8
    __shared__ float wc[169];       // combined 13x13 stencil
    int plane = blockIdx.x;
    int ch    = plane % CC;
    int tid   = threadIdx.x;

    float4 z4 = make_float4(0.f,0.f,0.f,0.f);
    for (int i = tid; i < (76*80)/4; i += 256) ((float4*)tile)[i] = z4;
    if (tid < 169) wc[tid] = 0.f;
    __syncthreads();
    if (tid < 33) { int a = tid/3  - 5, b = tid%3  - 1; wc[(a+6)*13 + (b+6)]   += wh1[ch*33 + tid]; }
    __syncthreads();
    if (tid < 33) { int a = tid/11 - 1, b = tid%11 - 5; wc[(a+6)*13 + (b+6)]   += wv1[ch*33 + tid]; }
    __syncthreads();
    if (tid < 33) { int a = tid/3  - 5, b = tid%3  - 1; wc[(a+6)*13 + (b-a+6)] += wh2[ch*33 + tid]; }
    __syncthreads();
    if (tid < 33) { int s = tid/11 - 1, t = tid%11 - 5; wc[(s-t+6)*13 + (t+6)] += wv2[ch*33 + tid]; }

    const float4* src = (const float4*)(g_xtem + (size_t)plane*(HT*HT));
    for (int i = tid; i < 1024; i += 256) {
        int r = i / 16, c4 = i % 16;
        *((float4*)&tile[(r+6)*80 + c4*4 + 8]) = src[i];
    }
    __syncthreads();

    int lane = tid & 31, w = tid >> 5;
    int c  = (w & 1)*32 + lane;
    int r0 = (w >> 1)*16;
    float acc[16];
    #pragma unroll
    for (int k = 0; k < 16; k++) acc[k] = 0.f;

    constexpr int LO[13] = {5,-1,-1,-1,-1,-5,-5,-5,-3,-4,-5,-6,-5};
    constexpr int HI[13] = {5, 6, 5, 4, 3, 5, 5, 5, 1, 1, 1, 1,-5};
    #pragma unroll
    for (int d = 0; d < 13; d++) {
        int cidx = c + d + 2;
        float xr[28];
        #pragma unroll
        for (int m = LO[d]+6; m <= HI[d]+21; m++)
            xr[m] = tile[(r0 + m)*80 + cidx];
        #pragma unroll
        for (int di = LO[d]; di <= HI[d]; di++) {
            float wv = wc[(di+6)*13 + d];
            #pragma unroll
            for (int k = 0; k < 16; k++)
                acc[k] += wv * xr[k + di + 6];
        }
    }

    float inv = gamma[ch] * rsqrtf(var[ch] + 1e-5f);
    float b2  = beta[ch] - mean[ch]*inv;
    float* gp = g_gate + (size_t)plane*(HT*HT);
    #pragma unroll
    for (int k = 0; k < 16; k++) {
        float a = acc[k]*inv + b2;
        gp[(r0 + k)*HT + c] = 1.f / (1.f + __expf(-a));
    }
}

// -------------------------------------------------------------------------
// Kernel 3: out = x * gate[i/3, j/3].  Block = (48,8): x = fixed float4-col,
// y = gate row; each thread does the 3 image rows sharing that gate row.
// Gate values + all index math loop-invariant; 3 batched LDG.128.
// grid (8, 1024).
// -------------------------------------------------------------------------
__global__ void __launch_bounds__(384) k_mul(const float* __restrict__ x,
                                             float* __restrict__ out) {
    __shared__ float gsm[8*64];        // 8 gate rows
    int plane = blockIdx.y;
    int grp   = blockIdx.x;            // 24-row group
    int qx    = threadIdx.x;           // float4 col 0..47
    int y     = threadIdx.y;           // gate row 0..7
    int tid   = y*48 + qx;

    const float4* gsrc = (const float4*)(g_gate + (size_t)plane*(HT*HT) + grp*8*HT);
    if (tid < 128) ((float4*)gsm)[tid] = gsrc[tid];
    __syncthreads();

    // loop-invariant gate values for this column quad
    int q3  = qx / 3;
    int rem = qx - q3*3;
    float lo = gsm[y*64 + 4*q3 + rem];
    float hi = gsm[y*64 + 4*q3 + rem + 1];
    float gy = (rem == 2) ? hi : lo;   // .y multiplier
    float gz = (rem >= 1) ? hi : lo;   // .z multiplier

    size_t base = (size_t)plane*9216 + (grp*24 + y*3)*48 + qx;
    const float4* xp = (const float4*)x + base;
    float4*       op = (float4*)out     + base;

    float4 v0 = __ldg(xp);
    float4 v1 = __ldg(xp + 48);
    float4 v2 = __ldg(xp + 96);

    float4 o0, o1, o2;
    o0.x = v0.x*lo; o0.y = v0.y*gy; o0.z = v0.z*gz; o0.w = v0.w*hi;
    o1.x = v1.x*lo; o1.y = v1.y*gy; o1.z = v1.z*gz; o1.w = v1.w*hi;
    o2.x = v2.x*lo; o2.y = v2.y*gy; o2.z = v2.z*gz; o2.w = v2.w*hi;
    op[0]  = o0;
    op[48] = o1;
    op[96] = o2;
}

extern "C" void kernel_launch(void* const* d_in, const int* in_sizes, int n_in,
                              void* d_out, int out_size) {
    const float* x     = (const float*)d_in[0];
    const float* wh1   = (const float*)d_in[1];
    const float* wv1   = (const float*)d_in[2];
    const float* wh2   = (const float*)d_in[3];
    const float* wv2   = (const float*)d_in[4];
    const float* gamma = (const float*)d_in[5];
    const float* beta  = (const float*)d_in[6];
    const float* mean  = (const float*)d_in[7];
    const float* var   = (const float*)d_in[8];
    float* out = (float*)d_out;

    k_pool<<<dim3(8, BB*CC), dim3(48, 5)>>>(x);
    k_att<<<BB*CC, 256>>>(wh1, wv1, wh2, wv2, gamma, beta, mean, var);
    k_mul<<<dim3(8, BB*CC), dim3(48, 8)>>>(x, out);
}